// round 1
// baseline (speedup 1.0000x reference)
#include <cuda_runtime.h>
#include <cuda_bf16.h>
#include <math.h>

// Problem constants (fixed shapes for this dataset)
#define NMAX 50000
#define EMAX 800000
#define ETOTMAX (NMAX + EMAX)
#define IN_DIM 128
#define HC 256      // H*C
#define HEADS 4
#define CDIM 64
#define NEG_SLOPE 0.2f

// ---------------- scratch (static device globals; no allocation) ----------------
__device__ float d_h[(size_t)NMAX * HC];        // projected features [N, 256]
__device__ float d_asrc[NMAX * HEADS];          // per-node src attention term
__device__ float d_adst[NMAX * HEADS];          // per-node dst attention term
__device__ float d_e[(size_t)ETOTMAX * HEADS];  // edge logits, then exp values (in place)
__device__ unsigned d_emaxu[NMAX * HEADS];      // segment max (order-preserving uint encoding)
__device__ float d_denom[NMAX * HEADS];         // segment softmax denominator
__device__ float d_accum[(size_t)NMAX * CDIM];  // head-summed output accumulator

// order-preserving float <-> uint (for atomicMax on floats incl. negatives)
__device__ __forceinline__ unsigned f2u(float f) {
    unsigned b = __float_as_uint(f);
    return (b & 0x80000000u) ? ~b : (b | 0x80000000u);
}
__device__ __forceinline__ float u2f(unsigned u) {
    unsigned b = (u & 0x80000000u) ? (u ^ 0x80000000u) : ~u;
    return __uint_as_float(b);
}

__device__ __forceinline__ float lrelu(float v) {
    return v > 0.0f ? v : NEG_SLOPE * v;
}

// ---------------- Kernel 1: SGEMM h = x @ W  ([N,128] x [128,256]) -------------
// Classic 64x64 tile, BK=16, 256 threads, 4x4 microtile per thread.
#define BM 64
#define BN 64
#define BK 16
__global__ void gemm_kernel(const float* __restrict__ A, const float* __restrict__ B, int M) {
    __shared__ float As[BK][BM];   // transposed A tile (rows 256B -> float4 aligned)
    __shared__ float Bs[BK][BN];

    int bx = blockIdx.x;           // 0..3 (column blocks of 64 = one head each)
    int by = blockIdx.y;
    int tid = threadIdx.x;
    int tx = tid & 15;
    int ty = tid >> 4;
    int row0 = by * BM;
    int col0 = bx * BN;

    float acc[4][4] = {};

    for (int kt = 0; kt < IN_DIM; kt += BK) {
        // load A tile: each thread loads one float4 of a row, scatters transposed
        {
            int r = tid >> 2;                 // 0..63
            int cs = (tid & 3) * 4;           // 0,4,8,12
            int grow = row0 + r;
            float4 v = make_float4(0.f, 0.f, 0.f, 0.f);
            if (grow < M) v = *(const float4*)(A + (size_t)grow * IN_DIM + kt + cs);
            As[cs + 0][r] = v.x; As[cs + 1][r] = v.y;
            As[cs + 2][r] = v.z; As[cs + 3][r] = v.w;
        }
        // load B tile: 16x64 = 256 float4-chunks of 4 -> each thread one float4
        {
            int r = tid >> 4;                 // 0..15
            int cs = (tid & 15) * 4;          // 0..60
            float4 v = *(const float4*)(B + (size_t)(kt + r) * HC + col0 + cs);
            *(float4*)(&Bs[r][cs]) = v;
        }
        __syncthreads();

        #pragma unroll
        for (int k = 0; k < BK; k++) {
            float4 a4 = *(const float4*)(&As[k][ty * 4]);
            float4 b4 = *(const float4*)(&Bs[k][tx * 4]);
            float a[4] = {a4.x, a4.y, a4.z, a4.w};
            float b[4] = {b4.x, b4.y, b4.z, b4.w};
            #pragma unroll
            for (int i = 0; i < 4; i++)
                #pragma unroll
                for (int j = 0; j < 4; j++)
                    acc[i][j] += a[i] * b[j];
        }
        __syncthreads();
    }

    #pragma unroll
    for (int i = 0; i < 4; i++) {
        int grow = row0 + ty * 4 + i;
        if (grow < M) {
            float4 v = make_float4(acc[i][0], acc[i][1], acc[i][2], acc[i][3]);
            *(float4*)(d_h + (size_t)grow * HC + col0 + tx * 4) = v;
        }
    }
}

// ---------------- Kernel 2: per-node attention terms ---------------------------
// one warp per node; per head: 2 coalesced loads per lane + shuffle reduce
__global__ void att_kernel(const float* __restrict__ att_src,
                           const float* __restrict__ att_dst, int N) {
    int warp = (blockIdx.x * blockDim.x + threadIdx.x) >> 5;
    int lane = threadIdx.x & 31;
    if (warp >= N) return;
    const float* hr = d_h + (size_t)warp * HC;
    #pragma unroll
    for (int hh = 0; hh < HEADS; hh++) {
        float v0 = hr[hh * CDIM + lane];
        float v1 = hr[hh * CDIM + 32 + lane];
        float s = v0 * __ldg(&att_src[hh * CDIM + lane]) + v1 * __ldg(&att_src[hh * CDIM + 32 + lane]);
        float d = v0 * __ldg(&att_dst[hh * CDIM + lane]) + v1 * __ldg(&att_dst[hh * CDIM + 32 + lane]);
        #pragma unroll
        for (int o = 16; o > 0; o >>= 1) {
            s += __shfl_xor_sync(0xFFFFFFFFu, s, o);
            d += __shfl_xor_sync(0xFFFFFFFFu, d, o);
        }
        if (lane == 0) {
            d_asrc[warp * HEADS + hh] = s;
            d_adst[warp * HEADS + hh] = d;
        }
    }
}

// ---------------- Kernel 3: init accumulators ----------------------------------
__global__ void init_kernel(int N) {
    int i = blockIdx.x * blockDim.x + threadIdx.x;
    if (i < N * CDIM) d_accum[i] = 0.0f;
    if (i < N * HEADS) { d_emaxu[i] = 0u; d_denom[i] = 0.0f; }  // u=0 encodes -inf-ish
}

// ---------------- Kernel 4: edge logits + segment max --------------------------
__global__ void edge_logits_kernel(const int* __restrict__ ei, int E, int N) {
    int i = blockIdx.x * blockDim.x + threadIdx.x;
    int Etot = E + N;
    if (i >= Etot) return;
    int s, d;
    if (i < E) { s = ei[i]; d = ei[E + i]; } else { s = d = i - E; }
    float4 as = *(const float4*)(d_asrc + s * HEADS);
    float4 ad = *(const float4*)(d_adst + d * HEADS);
    float e0 = lrelu(as.x + ad.x);
    float e1 = lrelu(as.y + ad.y);
    float e2 = lrelu(as.z + ad.z);
    float e3 = lrelu(as.w + ad.w);
    *(float4*)(d_e + (size_t)i * HEADS) = make_float4(e0, e1, e2, e3);
    unsigned* mp = d_emaxu + d * HEADS;
    atomicMax(&mp[0], f2u(e0));
    atomicMax(&mp[1], f2u(e1));
    atomicMax(&mp[2], f2u(e2));
    atomicMax(&mp[3], f2u(e3));
}

// ---------------- Kernel 5: exp + segment sum -----------------------------------
__global__ void edge_exp_kernel(const int* __restrict__ ei, int E, int N) {
    int i = blockIdx.x * blockDim.x + threadIdx.x;
    int Etot = E + N;
    if (i >= Etot) return;
    int d = (i < E) ? ei[E + i] : (i - E);
    float4 e = *(const float4*)(d_e + (size_t)i * HEADS);
    const unsigned* mp = d_emaxu + d * HEADS;
    float x0 = __expf(e.x - u2f(mp[0]));
    float x1 = __expf(e.y - u2f(mp[1]));
    float x2 = __expf(e.z - u2f(mp[2]));
    float x3 = __expf(e.w - u2f(mp[3]));
    *(float4*)(d_e + (size_t)i * HEADS) = make_float4(x0, x1, x2, x3);
    float* dp = d_denom + d * HEADS;
    atomicAdd(&dp[0], x0);
    atomicAdd(&dp[1], x1);
    atomicAdd(&dp[2], x2);
    atomicAdd(&dp[3], x3);
}

// ---------------- Kernel 6: weighted scatter (head-fused) ------------------------
// one warp per edge; each lane handles columns {lane, lane+32}; heads reduced in-register
__global__ void scatter_kernel(const int* __restrict__ ei, int E, int N) {
    int gw = (blockIdx.x * blockDim.x + threadIdx.x) >> 5;
    int lane = threadIdx.x & 31;
    int Etot = E + N;
    if (gw >= Etot) return;
    int s, d;
    if (gw < E) { s = ei[gw]; d = ei[E + gw]; } else { s = d = gw - E; }
    float4 ex = *(const float4*)(d_e + (size_t)gw * HEADS);
    float4 dn = *(const float4*)(d_denom + d * HEADS);
    float a0 = ex.x / dn.x;
    float a1 = ex.y / dn.y;
    float a2 = ex.z / dn.z;
    float a3 = ex.w / dn.w;
    const float* hs = d_h + (size_t)s * HC;
    float v0 = a0 * hs[lane]       + a1 * hs[64 + lane]
             + a2 * hs[128 + lane] + a3 * hs[192 + lane];
    float v1 = a0 * hs[32 + lane]  + a1 * hs[96 + lane]
             + a2 * hs[160 + lane] + a3 * hs[224 + lane];
    float* op = d_accum + (size_t)d * CDIM;
    atomicAdd(&op[lane], v0);
    atomicAdd(&op[32 + lane], v1);
}

// ---------------- Kernel 7: finalize: mean-over-heads + bias + ELU ---------------
__global__ void finalize_kernel(const float* __restrict__ bias, float* __restrict__ out, int N) {
    int i = blockIdx.x * blockDim.x + threadIdx.x;
    if (i >= N * CDIM) return;
    float v = d_accum[i] * 0.25f + __ldg(&bias[i & (CDIM - 1)]);
    out[i] = v > 0.0f ? v : expm1f(v);
}

// ---------------- launch ----------------------------------------------------------
extern "C" void kernel_launch(void* const* d_in, const int* in_sizes, int n_in,
                              void* d_out, int out_size) {
    const float* x       = (const float*)d_in[0];
    const int*   ei      = (const int*)d_in[1];
    const float* W       = (const float*)d_in[2];
    const float* att_src = (const float*)d_in[3];
    const float* att_dst = (const float*)d_in[4];
    const float* bias    = (const float*)d_in[5];
    float* out = (float*)d_out;

    int N = in_sizes[0] / IN_DIM;
    int E = in_sizes[1] / 2;
    int Etot = E + N;

    // 1. projection GEMM
    dim3 ggrid(HC / BN, (N + BM - 1) / BM);
    gemm_kernel<<<ggrid, 256>>>(x, W, N);

    // 2. per-node attention terms (warp per node)
    att_kernel<<<(N * 32 + 255) / 256, 256>>>(att_src, att_dst, N);

    // 3. init accumulators
    init_kernel<<<(N * CDIM + 255) / 256, 256>>>(N);

    // 4. edge logits + segment max
    edge_logits_kernel<<<(Etot + 255) / 256, 256>>>(ei, E, N);

    // 5. exp + segment sum
    edge_exp_kernel<<<(Etot + 255) / 256, 256>>>(ei, E, N);

    // 6. weighted scatter (warp per edge)
    long long sthreads = (long long)Etot * 32;
    scatter_kernel<<<(unsigned)((sthreads + 255) / 256), 256>>>(ei, E, N);

    // 7. finalize
    finalize_kernel<<<(N * CDIM + 255) / 256, 256>>>(bias, out, N);
}

// round 2
// speedup vs baseline: 1.1108x; 1.1108x over previous
#include <cuda_runtime.h>
#include <cuda_bf16.h>
#include <math.h>

#define NMAX 50000
#define EMAX 800000
#define ETOTMAX (NMAX + EMAX)
#define IN_DIM 128
#define HC 256
#define HEADS 4
#define CDIM 64
#define NEG_SLOPE 0.2f

// ---------------- scratch ----------------
__device__ float d_h[(size_t)NMAX * HC];
__device__ float d_asrc[NMAX * HEADS];
__device__ float d_adst[NMAX * HEADS];
__device__ float d_e[(size_t)ETOTMAX * HEADS];   // exp(logit) per edge
__device__ float d_denom[NMAX * HEADS];
__device__ float d_accum[(size_t)NMAX * CDIM];

__device__ __forceinline__ float lrelu(float v) {
    return v > 0.0f ? v : NEG_SLOPE * v;
}

// ---------------- Kernel 1: SGEMM h = x @ W with FFMA2 + fused att epilogue ----
#define BM 64
#define BN 64
#define BK 16
__global__ void gemm_kernel(const float* __restrict__ A, const float* __restrict__ B,
                            const float* __restrict__ att_src,
                            const float* __restrict__ att_dst, int M) {
    __shared__ float As[BK][BM];
    __shared__ float Bs[BK][BN];

    int bx = blockIdx.x;           // head (BN == CDIM)
    int by = blockIdx.y;
    int tid = threadIdx.x;
    int tx = tid & 15;
    int ty = tid >> 4;
    int row0 = by * BM;
    int col0 = bx * BN;

    unsigned long long acc64[4][2];
    #pragma unroll
    for (int i = 0; i < 4; i++) { acc64[i][0] = 0ULL; acc64[i][1] = 0ULL; }

    for (int kt = 0; kt < IN_DIM; kt += BK) {
        {
            int r = tid >> 2;
            int cs = (tid & 3) * 4;
            int grow = row0 + r;
            float4 v = make_float4(0.f, 0.f, 0.f, 0.f);
            if (grow < M) v = *(const float4*)(A + (size_t)grow * IN_DIM + kt + cs);
            As[cs + 0][r] = v.x; As[cs + 1][r] = v.y;
            As[cs + 2][r] = v.z; As[cs + 3][r] = v.w;
        }
        {
            int r = tid >> 4;
            int cs = (tid & 15) * 4;
            float4 v = *(const float4*)(B + (size_t)(kt + r) * HC + col0 + cs);
            *(float4*)(&Bs[r][cs]) = v;
        }
        __syncthreads();

        #pragma unroll
        for (int k = 0; k < BK; k++) {
            float4 a4 = *(const float4*)(&As[k][ty * 4]);
            const unsigned long long* bp = (const unsigned long long*)(&Bs[k][tx * 4]);
            unsigned long long b01 = bp[0];
            unsigned long long b23 = bp[1];
            float a[4] = {a4.x, a4.y, a4.z, a4.w};
            #pragma unroll
            for (int i = 0; i < 4; i++) {
                unsigned long long ad;
                asm("mov.b64 %0, {%1, %1};" : "=l"(ad) : "f"(a[i]));
                asm("fma.rn.f32x2 %0, %1, %2, %0;" : "+l"(acc64[i][0]) : "l"(ad), "l"(b01));
                asm("fma.rn.f32x2 %0, %1, %2, %0;" : "+l"(acc64[i][1]) : "l"(ad), "l"(b23));
            }
        }
        __syncthreads();
    }

    // unpack accumulators
    float accf[4][4];
    #pragma unroll
    for (int i = 0; i < 4; i++) {
        asm("mov.b64 {%0, %1}, %2;" : "=f"(accf[i][0]), "=f"(accf[i][1]) : "l"(acc64[i][0]));
        asm("mov.b64 {%0, %1}, %2;" : "=f"(accf[i][2]), "=f"(accf[i][3]) : "l"(acc64[i][1]));
    }

    // store h tile
    #pragma unroll
    for (int i = 0; i < 4; i++) {
        int grow = row0 + ty * 4 + i;
        if (grow < M) {
            float4 v = make_float4(accf[i][0], accf[i][1], accf[i][2], accf[i][3]);
            *(float4*)(d_h + (size_t)grow * HC + col0 + tx * 4) = v;
        }
    }

    // fused attention-dot epilogue: this block owns the full C=64 of head bx
    int head = bx;
    float sw[4], dw[4];
    #pragma unroll
    for (int j = 0; j < 4; j++) {
        sw[j] = __ldg(&att_src[head * CDIM + tx * 4 + j]);
        dw[j] = __ldg(&att_dst[head * CDIM + tx * 4 + j]);
    }
    #pragma unroll
    for (int i = 0; i < 4; i++) {
        float s = accf[i][0] * sw[0] + accf[i][1] * sw[1]
                + accf[i][2] * sw[2] + accf[i][3] * sw[3];
        float dd = accf[i][0] * dw[0] + accf[i][1] * dw[1]
                 + accf[i][2] * dw[2] + accf[i][3] * dw[3];
        #pragma unroll
        for (int o = 1; o < 16; o <<= 1) {
            s  += __shfl_xor_sync(0xFFFFFFFFu, s, o);
            dd += __shfl_xor_sync(0xFFFFFFFFu, dd, o);
        }
        int grow = row0 + ty * 4 + i;
        if (tx == 0 && grow < M) {
            d_asrc[grow * HEADS + head] = s;
            d_adst[grow * HEADS + head] = dd;
        }
    }
}

// ---------------- Kernel 2: init accumulators -----------------------------------
__global__ void init_kernel(int N) {
    int i = blockIdx.x * blockDim.x + threadIdx.x;
    if (i < N * CDIM) d_accum[i] = 0.0f;
    if (i < N * HEADS) d_denom[i] = 0.0f;
}

// ---------------- Kernel 3: fused logits + exp + denominator --------------------
// (softmax shift removed: logits are bounded ~|e|<10, exp safe, mathematically
//  identical by shift invariance)
__global__ void edge_kernel(const int* __restrict__ ei, int E, int N) {
    int i = blockIdx.x * blockDim.x + threadIdx.x;
    int Etot = E + N;
    if (i >= Etot) return;
    int s, d;
    if (i < E) { s = ei[i]; d = ei[E + i]; } else { s = d = i - E; }
    float4 as = *(const float4*)(d_asrc + s * HEADS);
    float4 ad = *(const float4*)(d_adst + d * HEADS);
    float x0 = __expf(lrelu(as.x + ad.x));
    float x1 = __expf(lrelu(as.y + ad.y));
    float x2 = __expf(lrelu(as.z + ad.z));
    float x3 = __expf(lrelu(as.w + ad.w));
    *(float4*)(d_e + (size_t)i * HEADS) = make_float4(x0, x1, x2, x3);
    float* dp = d_denom + d * HEADS;
    atomicAdd(&dp[0], x0);
    atomicAdd(&dp[1], x1);
    atomicAdd(&dp[2], x2);
    atomicAdd(&dp[3], x3);
}

// ---------------- Kernel 4: weighted scatter (head-fused, float2 lanes) ---------
__global__ void scatter_kernel(const int* __restrict__ ei, int E, int N) {
    int gw = (blockIdx.x * blockDim.x + threadIdx.x) >> 5;
    int lane = threadIdx.x & 31;
    int Etot = E + N;
    if (gw >= Etot) return;
    int s, d;
    if (gw < E) { s = ei[gw]; d = ei[E + gw]; } else { s = d = gw - E; }
    float4 ex = *(const float4*)(d_e + (size_t)gw * HEADS);
    float4 dn = *(const float4*)(d_denom + d * HEADS);
    float a0 = ex.x / dn.x;
    float a1 = ex.y / dn.y;
    float a2 = ex.z / dn.z;
    float a3 = ex.w / dn.w;
    const float2* hs = (const float2*)(d_h + (size_t)s * HC);
    float2 h0 = hs[lane];
    float2 h1 = hs[32 + lane];
    float2 h2 = hs[64 + lane];
    float2 h3 = hs[96 + lane];
    float vx = a0 * h0.x + a1 * h1.x + a2 * h2.x + a3 * h3.x;
    float vy = a0 * h0.y + a1 * h1.y + a2 * h2.y + a3 * h3.y;
    float* op = d_accum + (size_t)d * CDIM + lane * 2;
    atomicAdd(op, vx);
    atomicAdd(op + 1, vy);
}

// ---------------- Kernel 5: finalize --------------------------------------------
__global__ void finalize_kernel(const float* __restrict__ bias, float* __restrict__ out, int N) {
    int i = blockIdx.x * blockDim.x + threadIdx.x;
    if (i >= N * CDIM) return;
    float v = d_accum[i] * 0.25f + __ldg(&bias[i & (CDIM - 1)]);
    out[i] = v > 0.0f ? v : expm1f(v);
}

// ---------------- launch ---------------------------------------------------------
extern "C" void kernel_launch(void* const* d_in, const int* in_sizes, int n_in,
                              void* d_out, int out_size) {
    const float* x       = (const float*)d_in[0];
    const int*   ei      = (const int*)d_in[1];
    const float* W       = (const float*)d_in[2];
    const float* att_src = (const float*)d_in[3];
    const float* att_dst = (const float*)d_in[4];
    const float* bias    = (const float*)d_in[5];
    float* out = (float*)d_out;

    int N = in_sizes[0] / IN_DIM;
    int E = in_sizes[1] / 2;
    int Etot = E + N;

    dim3 ggrid(HC / BN, (N + BM - 1) / BM);
    gemm_kernel<<<ggrid, 256>>>(x, W, att_src, att_dst, N);

    init_kernel<<<(N * CDIM + 255) / 256, 256>>>(N);

    edge_kernel<<<(Etot + 255) / 256, 256>>>(ei, E, N);

    long long sthreads = (long long)Etot * 32;
    scatter_kernel<<<(unsigned)((sthreads + 255) / 256), 256>>>(ei, E, N);

    finalize_kernel<<<(N * CDIM + 255) / 256, 256>>>(bias, out, N);
}

// round 3
// speedup vs baseline: 1.5324x; 1.3795x over previous
#include <cuda_runtime.h>
#include <cuda_bf16.h>
#include <math.h>

#define NMAX 50000
#define EMAX 800000
#define ETOTMAX (NMAX + EMAX)
#define IN_DIM 128
#define HC 256
#define HEADS 4
#define CDIM 64
#define NEG_SLOPE 0.2f
#define SCAN_B 512

// ---------------- scratch ----------------
__device__ float d_h[(size_t)NMAX * HC];
__device__ float d_asrc[NMAX * HEADS];
__device__ float d_adst[NMAX * HEADS];
__device__ float d_alpha[(size_t)ETOTMAX * HEADS];
__device__ float d_dinv[NMAX * HEADS];        // inverse softmax denominator
__device__ int d_deg[NMAX];
__device__ int d_ptr[NMAX];
__device__ int d_work[NMAX];
__device__ int d_csr_src[ETOTMAX];
__device__ int d_csr_dst[ETOTMAX];
__device__ int d_blocksums[SCAN_B];
__device__ int d_blockoff[SCAN_B];

__device__ __forceinline__ float lrelu(float v) {
    return v > 0.0f ? v : NEG_SLOPE * v;
}

// ---------------- Kernel 1: SGEMM h = x @ W (FFMA2) + fused att epilogue -------
#define BM 64
#define BN 64
#define BK 16
__global__ void gemm_kernel(const float* __restrict__ A, const float* __restrict__ B,
                            const float* __restrict__ att_src,
                            const float* __restrict__ att_dst, int M) {
    __shared__ float As[BK][BM];
    __shared__ float Bs[BK][BN];

    int bx = blockIdx.x;           // head
    int by = blockIdx.y;
    int tid = threadIdx.x;
    int tx = tid & 15;
    int ty = tid >> 4;
    int row0 = by * BM;
    int col0 = bx * BN;

    unsigned long long acc64[4][2];
    #pragma unroll
    for (int i = 0; i < 4; i++) { acc64[i][0] = 0ULL; acc64[i][1] = 0ULL; }

    for (int kt = 0; kt < IN_DIM; kt += BK) {
        {
            int r = tid >> 2;
            int cs = (tid & 3) * 4;
            int grow = row0 + r;
            float4 v = make_float4(0.f, 0.f, 0.f, 0.f);
            if (grow < M) v = *(const float4*)(A + (size_t)grow * IN_DIM + kt + cs);
            As[cs + 0][r] = v.x; As[cs + 1][r] = v.y;
            As[cs + 2][r] = v.z; As[cs + 3][r] = v.w;
        }
        {
            int r = tid >> 4;
            int cs = (tid & 15) * 4;
            float4 v = *(const float4*)(B + (size_t)(kt + r) * HC + col0 + cs);
            *(float4*)(&Bs[r][cs]) = v;
        }
        __syncthreads();

        #pragma unroll
        for (int k = 0; k < BK; k++) {
            float4 a4 = *(const float4*)(&As[k][ty * 4]);
            const unsigned long long* bp = (const unsigned long long*)(&Bs[k][tx * 4]);
            unsigned long long b01 = bp[0];
            unsigned long long b23 = bp[1];
            float a[4] = {a4.x, a4.y, a4.z, a4.w};
            #pragma unroll
            for (int i = 0; i < 4; i++) {
                unsigned long long ad;
                asm("mov.b64 %0, {%1, %1};" : "=l"(ad) : "f"(a[i]));
                asm("fma.rn.f32x2 %0, %1, %2, %0;" : "+l"(acc64[i][0]) : "l"(ad), "l"(b01));
                asm("fma.rn.f32x2 %0, %1, %2, %0;" : "+l"(acc64[i][1]) : "l"(ad), "l"(b23));
            }
        }
        __syncthreads();
    }

    float accf[4][4];
    #pragma unroll
    for (int i = 0; i < 4; i++) {
        asm("mov.b64 {%0, %1}, %2;" : "=f"(accf[i][0]), "=f"(accf[i][1]) : "l"(acc64[i][0]));
        asm("mov.b64 {%0, %1}, %2;" : "=f"(accf[i][2]), "=f"(accf[i][3]) : "l"(acc64[i][1]));
    }

    #pragma unroll
    for (int i = 0; i < 4; i++) {
        int grow = row0 + ty * 4 + i;
        if (grow < M) {
            float4 v = make_float4(accf[i][0], accf[i][1], accf[i][2], accf[i][3]);
            *(float4*)(d_h + (size_t)grow * HC + col0 + tx * 4) = v;
        }
    }

    int head = bx;
    float sw[4], dw[4];
    #pragma unroll
    for (int j = 0; j < 4; j++) {
        sw[j] = __ldg(&att_src[head * CDIM + tx * 4 + j]);
        dw[j] = __ldg(&att_dst[head * CDIM + tx * 4 + j]);
    }
    #pragma unroll
    for (int i = 0; i < 4; i++) {
        float s = accf[i][0] * sw[0] + accf[i][1] * sw[1]
                + accf[i][2] * sw[2] + accf[i][3] * sw[3];
        float dd = accf[i][0] * dw[0] + accf[i][1] * dw[1]
                 + accf[i][2] * dw[2] + accf[i][3] * dw[3];
        #pragma unroll
        for (int o = 1; o < 16; o <<= 1) {
            s  += __shfl_xor_sync(0xFFFFFFFFu, s, o);
            dd += __shfl_xor_sync(0xFFFFFFFFu, dd, o);
        }
        int grow = row0 + ty * 4 + i;
        if (tx == 0 && grow < M) {
            d_asrc[grow * HEADS + head] = s;
            d_adst[grow * HEADS + head] = dd;
        }
    }
}

// ---------------- CSR build ------------------------------------------------------
__global__ void deg_init_kernel(int N) {
    int i = blockIdx.x * blockDim.x + threadIdx.x;
    if (i < N) d_deg[i] = 1;   // self loop
}

__global__ void deg_hist_kernel(const int* __restrict__ ei, int E) {
    int i = blockIdx.x * blockDim.x + threadIdx.x;
    if (i < E) atomicAdd(&d_deg[ei[E + i]], 1);
}

__global__ void scan1_kernel(int N) {
    __shared__ int sm[SCAN_B];
    int b = blockIdx.x, t = threadIdx.x;
    int i = b * SCAN_B + t;
    int v = (i < N) ? d_deg[i] : 0;
    sm[t] = v;
    __syncthreads();
    #pragma unroll
    for (int o = 1; o < SCAN_B; o <<= 1) {
        int x = (t >= o) ? sm[t - o] : 0;
        __syncthreads();
        sm[t] += x;
        __syncthreads();
    }
    if (i < N) d_ptr[i] = sm[t] - v;          // exclusive
    if (t == SCAN_B - 1) d_blocksums[b] = sm[t];
}

__global__ void scan2_kernel(int nblocks) {
    __shared__ int sm[SCAN_B];
    int t = threadIdx.x;
    int v = (t < nblocks) ? d_blocksums[t] : 0;
    sm[t] = v;
    __syncthreads();
    #pragma unroll
    for (int o = 1; o < SCAN_B; o <<= 1) {
        int x = (t >= o) ? sm[t - o] : 0;
        __syncthreads();
        sm[t] += x;
        __syncthreads();
    }
    if (t < nblocks) d_blockoff[t] = sm[t] - v;
}

__global__ void scan3_kernel(int N) {
    int i = blockIdx.x * blockDim.x + threadIdx.x;
    if (i < N) {
        int p = d_ptr[i] + d_blockoff[i / SCAN_B];
        d_ptr[i] = p;
        d_work[i] = p;
    }
}

__global__ void fill_kernel(const int* __restrict__ ei, int E, int N) {
    int i = blockIdx.x * blockDim.x + threadIdx.x;
    int Etot = E + N;
    if (i >= Etot) return;
    int s, d;
    if (i < E) { s = ei[i]; d = ei[E + i]; } else { s = d = i - E; }
    int pos = atomicAdd(&d_work[d], 1);
    d_csr_src[pos] = s;
    d_csr_dst[pos] = d;
}

// ---------------- denominator (warp per node, no atomics) ------------------------
__global__ void denom_kernel(int N) {
    int w = (blockIdx.x * blockDim.x + threadIdx.x) >> 5;
    int lane = threadIdx.x & 31;
    if (w >= N) return;
    int r0 = d_ptr[w];
    int r1 = r0 + d_deg[w];
    float4 ad = *(const float4*)(d_adst + w * HEADS);
    float dn0 = 0.f, dn1 = 0.f, dn2 = 0.f, dn3 = 0.f;
    for (int i = r0 + lane; i < r1; i += 32) {
        int s = d_csr_src[i];
        float4 as = *(const float4*)(d_asrc + s * HEADS);
        dn0 += __expf(lrelu(as.x + ad.x));
        dn1 += __expf(lrelu(as.y + ad.y));
        dn2 += __expf(lrelu(as.z + ad.z));
        dn3 += __expf(lrelu(as.w + ad.w));
    }
    #pragma unroll
    for (int o = 16; o > 0; o >>= 1) {
        dn0 += __shfl_xor_sync(0xFFFFFFFFu, dn0, o);
        dn1 += __shfl_xor_sync(0xFFFFFFFFu, dn1, o);
        dn2 += __shfl_xor_sync(0xFFFFFFFFu, dn2, o);
        dn3 += __shfl_xor_sync(0xFFFFFFFFu, dn3, o);
    }
    if (lane == 0) {
        *(float4*)(d_dinv + w * HEADS) =
            make_float4(1.f / dn0, 1.f / dn1, 1.f / dn2, 1.f / dn3);
    }
}

// ---------------- alpha (edge parallel, coalesced writes) ------------------------
__global__ void alpha_kernel(int Etot) {
    int i = blockIdx.x * blockDim.x + threadIdx.x;
    if (i >= Etot) return;
    int s = d_csr_src[i];
    int d = d_csr_dst[i];
    float4 as = *(const float4*)(d_asrc + s * HEADS);
    float4 ad = *(const float4*)(d_adst + d * HEADS);
    float4 iv = *(const float4*)(d_dinv + d * HEADS);
    float4 a;
    a.x = __expf(lrelu(as.x + ad.x)) * iv.x;
    a.y = __expf(lrelu(as.y + ad.y)) * iv.y;
    a.z = __expf(lrelu(as.z + ad.z)) * iv.z;
    a.w = __expf(lrelu(as.w + ad.w)) * iv.w;
    *(float4*)(d_alpha + (size_t)i * HEADS) = a;
}

// ---------------- aggregate (warp per node, no atomics, fused finalize) ----------
__device__ __forceinline__ void agg_edge(int i, int lane, float& accx, float& accy) {
    int s = __ldg(&d_csr_src[i]);
    float4 a = *(const float4*)(d_alpha + (size_t)i * HEADS);
    const float2* hs = (const float2*)(d_h + (size_t)s * HC);
    float2 h0 = hs[lane];
    float2 h1 = hs[32 + lane];
    float2 h2 = hs[64 + lane];
    float2 h3 = hs[96 + lane];
    accx += a.x * h0.x + a.y * h1.x + a.z * h2.x + a.w * h3.x;
    accy += a.x * h0.y + a.y * h1.y + a.z * h2.y + a.w * h3.y;
}

__global__ void aggregate_kernel(const float* __restrict__ bias,
                                 float* __restrict__ out, int N) {
    int w = (blockIdx.x * blockDim.x + threadIdx.x) >> 5;
    int lane = threadIdx.x & 31;
    if (w >= N) return;
    int r0 = d_ptr[w];
    int r1 = r0 + d_deg[w];
    float accx = 0.f, accy = 0.f;
    int i = r0;
    for (; i + 2 <= r1; i += 2) {
        agg_edge(i, lane, accx, accy);
        agg_edge(i + 1, lane, accx, accy);
    }
    if (i < r1) agg_edge(i, lane, accx, accy);

    float vx = accx * 0.25f + __ldg(&bias[lane * 2]);
    float vy = accy * 0.25f + __ldg(&bias[lane * 2 + 1]);
    float2 o;
    o.x = vx > 0.f ? vx : expm1f(vx);
    o.y = vy > 0.f ? vy : expm1f(vy);
    *(float2*)(out + (size_t)w * CDIM + lane * 2) = o;
}

// ---------------- launch ---------------------------------------------------------
extern "C" void kernel_launch(void* const* d_in, const int* in_sizes, int n_in,
                              void* d_out, int out_size) {
    const float* x       = (const float*)d_in[0];
    const int*   ei      = (const int*)d_in[1];
    const float* W       = (const float*)d_in[2];
    const float* att_src = (const float*)d_in[3];
    const float* att_dst = (const float*)d_in[4];
    const float* bias    = (const float*)d_in[5];
    float* out = (float*)d_out;

    int N = in_sizes[0] / IN_DIM;
    int E = in_sizes[1] / 2;
    int Etot = E + N;
    int nblocks = (N + SCAN_B - 1) / SCAN_B;

    dim3 ggrid(HC / BN, (N + BM - 1) / BM);
    gemm_kernel<<<ggrid, 256>>>(x, W, att_src, att_dst, N);

    deg_init_kernel<<<(N + 255) / 256, 256>>>(N);
    deg_hist_kernel<<<(E + 255) / 256, 256>>>(ei, E);
    scan1_kernel<<<nblocks, SCAN_B>>>(N);
    scan2_kernel<<<1, SCAN_B>>>(nblocks);
    scan3_kernel<<<(N + 255) / 256, 256>>>(N);
    fill_kernel<<<(Etot + 255) / 256, 256>>>(ei, E, N);

    denom_kernel<<<(N * 32 + 255) / 256, 256>>>(N);
    alpha_kernel<<<(Etot + 255) / 256, 256>>>(Etot);
    aggregate_kernel<<<(N * 32 + 255) / 256, 256>>>(bias, out, N);
}

// round 4
// speedup vs baseline: 1.5983x; 1.0430x over previous
#include <cuda_runtime.h>
#include <cuda_bf16.h>
#include <cuda_fp16.h>
#include <math.h>

#define NMAX 50000
#define EMAX 800000
#define ETOTMAX (NMAX + EMAX)
#define IN_DIM 128
#define HC 256
#define HEADS 4
#define CDIM 64
#define NEG_SLOPE 0.2f
#define SCAN_B 512

// ---------------- scratch ----------------
__device__ __half d_hh[(size_t)NMAX * HC];    // projected features, fp16 [N, 256]
__device__ float d_asrc[NMAX * HEADS];
__device__ float d_adst[NMAX * HEADS];
__device__ int d_deg[NMAX];
__device__ int d_ptr[NMAX];
__device__ int d_work[NMAX];
__device__ int d_csr_src[ETOTMAX];
__device__ int d_blocksums[SCAN_B];
__device__ int d_blockoff[SCAN_B];

__device__ __forceinline__ float lrelu(float v) {
    return v > 0.0f ? v : NEG_SLOPE * v;
}

// ---------------- Kernel 1: SGEMM h = x @ W (FFMA2) + fused att epilogue -------
#define BM 64
#define BN 64
#define BK 16
__global__ void gemm_kernel(const float* __restrict__ A, const float* __restrict__ B,
                            const float* __restrict__ att_src,
                            const float* __restrict__ att_dst, int M) {
    __shared__ float As[BK][BM];
    __shared__ float Bs[BK][BN];

    int bx = blockIdx.x;           // head
    int by = blockIdx.y;
    int tid = threadIdx.x;
    int tx = tid & 15;
    int ty = tid >> 4;
    int row0 = by * BM;
    int col0 = bx * BN;

    unsigned long long acc64[4][2];
    #pragma unroll
    for (int i = 0; i < 4; i++) { acc64[i][0] = 0ULL; acc64[i][1] = 0ULL; }

    for (int kt = 0; kt < IN_DIM; kt += BK) {
        {
            int r = tid >> 2;
            int cs = (tid & 3) * 4;
            int grow = row0 + r;
            float4 v = make_float4(0.f, 0.f, 0.f, 0.f);
            if (grow < M) v = *(const float4*)(A + (size_t)grow * IN_DIM + kt + cs);
            As[cs + 0][r] = v.x; As[cs + 1][r] = v.y;
            As[cs + 2][r] = v.z; As[cs + 3][r] = v.w;
        }
        {
            int r = tid >> 4;
            int cs = (tid & 15) * 4;
            float4 v = *(const float4*)(B + (size_t)(kt + r) * HC + col0 + cs);
            *(float4*)(&Bs[r][cs]) = v;
        }
        __syncthreads();

        #pragma unroll
        for (int k = 0; k < BK; k++) {
            float4 a4 = *(const float4*)(&As[k][ty * 4]);
            const unsigned long long* bp = (const unsigned long long*)(&Bs[k][tx * 4]);
            unsigned long long b01 = bp[0];
            unsigned long long b23 = bp[1];
            float a[4] = {a4.x, a4.y, a4.z, a4.w};
            #pragma unroll
            for (int i = 0; i < 4; i++) {
                unsigned long long ad;
                asm("mov.b64 %0, {%1, %1};" : "=l"(ad) : "f"(a[i]));
                asm("fma.rn.f32x2 %0, %1, %2, %0;" : "+l"(acc64[i][0]) : "l"(ad), "l"(b01));
                asm("fma.rn.f32x2 %0, %1, %2, %0;" : "+l"(acc64[i][1]) : "l"(ad), "l"(b23));
            }
        }
        __syncthreads();
    }

    float accf[4][4];
    #pragma unroll
    for (int i = 0; i < 4; i++) {
        asm("mov.b64 {%0, %1}, %2;" : "=f"(accf[i][0]), "=f"(accf[i][1]) : "l"(acc64[i][0]));
        asm("mov.b64 {%0, %1}, %2;" : "=f"(accf[i][2]), "=f"(accf[i][3]) : "l"(acc64[i][1]));
    }

    // store h tile as fp16 (only consumer is the fp16 aggregation pass)
    #pragma unroll
    for (int i = 0; i < 4; i++) {
        int grow = row0 + ty * 4 + i;
        if (grow < M) {
            __half2 p0 = __floats2half2_rn(accf[i][0], accf[i][1]);
            __half2 p1 = __floats2half2_rn(accf[i][2], accf[i][3]);
            uint2 pk;
            pk.x = *(unsigned*)&p0;
            pk.y = *(unsigned*)&p1;
            *(uint2*)(d_hh + (size_t)grow * HC + col0 + tx * 4) = pk;
        }
    }

    // fused attention-dot epilogue (fp32 accumulators -> full precision)
    int head = bx;
    float sw[4], dw[4];
    #pragma unroll
    for (int j = 0; j < 4; j++) {
        sw[j] = __ldg(&att_src[head * CDIM + tx * 4 + j]);
        dw[j] = __ldg(&att_dst[head * CDIM + tx * 4 + j]);
    }
    #pragma unroll
    for (int i = 0; i < 4; i++) {
        float s = accf[i][0] * sw[0] + accf[i][1] * sw[1]
                + accf[i][2] * sw[2] + accf[i][3] * sw[3];
        float dd = accf[i][0] * dw[0] + accf[i][1] * dw[1]
                 + accf[i][2] * dw[2] + accf[i][3] * dw[3];
        #pragma unroll
        for (int o = 1; o < 16; o <<= 1) {
            s  += __shfl_xor_sync(0xFFFFFFFFu, s, o);
            dd += __shfl_xor_sync(0xFFFFFFFFu, dd, o);
        }
        int grow = row0 + ty * 4 + i;
        if (tx == 0 && grow < M) {
            d_asrc[grow * HEADS + head] = s;
            d_adst[grow * HEADS + head] = dd;
        }
    }
}

// ---------------- CSR build ------------------------------------------------------
__global__ void deg_init_kernel(int N) {
    int i = blockIdx.x * blockDim.x + threadIdx.x;
    if (i < N) d_deg[i] = 1;   // self loop
}

__global__ void deg_hist_kernel(const int* __restrict__ ei, int E) {
    int i = blockIdx.x * blockDim.x + threadIdx.x;
    if (i < E) atomicAdd(&d_deg[ei[E + i]], 1);
}

__global__ void scan1_kernel(int N) {
    __shared__ int sm[SCAN_B];
    int b = blockIdx.x, t = threadIdx.x;
    int i = b * SCAN_B + t;
    int v = (i < N) ? d_deg[i] : 0;
    sm[t] = v;
    __syncthreads();
    #pragma unroll
    for (int o = 1; o < SCAN_B; o <<= 1) {
        int x = (t >= o) ? sm[t - o] : 0;
        __syncthreads();
        sm[t] += x;
        __syncthreads();
    }
    if (i < N) d_ptr[i] = sm[t] - v;          // exclusive
    if (t == SCAN_B - 1) d_blocksums[b] = sm[t];
}

__global__ void scan2_kernel(int nblocks) {
    __shared__ int sm[SCAN_B];
    int t = threadIdx.x;
    int v = (t < nblocks) ? d_blocksums[t] : 0;
    sm[t] = v;
    __syncthreads();
    #pragma unroll
    for (int o = 1; o < SCAN_B; o <<= 1) {
        int x = (t >= o) ? sm[t - o] : 0;
        __syncthreads();
        sm[t] += x;
        __syncthreads();
    }
    if (t < nblocks) d_blockoff[t] = sm[t] - v;
}

__global__ void scan3_kernel(int N) {
    int i = blockIdx.x * blockDim.x + threadIdx.x;
    if (i < N) {
        int p = d_ptr[i] + d_blockoff[i / SCAN_B];
        d_ptr[i] = p;
        d_work[i] = p;
    }
}

__global__ void fill_kernel(const int* __restrict__ ei, int E, int N) {
    int i = blockIdx.x * blockDim.x + threadIdx.x;
    int Etot = E + N;
    if (i >= Etot) return;
    int s, d;
    if (i < E) { s = ei[i]; d = ei[E + i]; } else { s = d = i - E; }
    int pos = atomicAdd(&d_work[d], 1);
    d_csr_src[pos] = s;
}

// ---------------- fused softmax + aggregate (warp per node, single edge pass) ----
// Accumulates unnormalized per-head numerators and denominators simultaneously;
// divides per-head at the end. Identical math to segment-softmax (shift-invariant,
// logits bounded so exp is fp32-safe).
__device__ __forceinline__ void agg_edge(int i, int lane, const float4& ad,
                                         float* num_x, float* num_y, float* dn) {
    int s = __ldg(&d_csr_src[i]);
    float4 as = *(const float4*)(d_asrc + s * HEADS);
    float e0 = __expf(lrelu(as.x + ad.x));
    float e1 = __expf(lrelu(as.y + ad.y));
    float e2 = __expf(lrelu(as.z + ad.z));
    float e3 = __expf(lrelu(as.w + ad.w));
    const __half2* hs = (const __half2*)(d_hh + (size_t)s * HC);
    float2 f0 = __half22float2(hs[lane]);
    float2 f1 = __half22float2(hs[32 + lane]);
    float2 f2 = __half22float2(hs[64 + lane]);
    float2 f3 = __half22float2(hs[96 + lane]);
    num_x[0] += e0 * f0.x;  num_y[0] += e0 * f0.y;
    num_x[1] += e1 * f1.x;  num_y[1] += e1 * f1.y;
    num_x[2] += e2 * f2.x;  num_y[2] += e2 * f2.y;
    num_x[3] += e3 * f3.x;  num_y[3] += e3 * f3.y;
    dn[0] += e0; dn[1] += e1; dn[2] += e2; dn[3] += e3;
}

__global__ void aggregate_kernel(const float* __restrict__ bias,
                                 float* __restrict__ out, int N) {
    int w = (blockIdx.x * blockDim.x + threadIdx.x) >> 5;
    int lane = threadIdx.x & 31;
    if (w >= N) return;
    int r0 = d_ptr[w];
    int r1 = r0 + d_deg[w];
    float4 ad = *(const float4*)(d_adst + w * HEADS);

    float num_x[4] = {0.f, 0.f, 0.f, 0.f};
    float num_y[4] = {0.f, 0.f, 0.f, 0.f};
    float dn[4] = {0.f, 0.f, 0.f, 0.f};

    int i = r0;
    for (; i + 2 <= r1; i += 2) {
        agg_edge(i, lane, ad, num_x, num_y, dn);
        agg_edge(i + 1, lane, ad, num_x, num_y, dn);
    }
    if (i < r1) agg_edge(i, lane, ad, num_x, num_y, dn);

    float i0 = 1.f / dn[0], i1 = 1.f / dn[1], i2 = 1.f / dn[2], i3 = 1.f / dn[3];
    float vx = (num_x[0] * i0 + num_x[1] * i1 + num_x[2] * i2 + num_x[3] * i3) * 0.25f
             + __ldg(&bias[lane * 2]);
    float vy = (num_y[0] * i0 + num_y[1] * i1 + num_y[2] * i2 + num_y[3] * i3) * 0.25f
             + __ldg(&bias[lane * 2 + 1]);
    float2 o;
    o.x = vx > 0.f ? vx : expm1f(vx);
    o.y = vy > 0.f ? vy : expm1f(vy);
    *(float2*)(out + (size_t)w * CDIM + lane * 2) = o;
}

// ---------------- launch ---------------------------------------------------------
extern "C" void kernel_launch(void* const* d_in, const int* in_sizes, int n_in,
                              void* d_out, int out_size) {
    const float* x       = (const float*)d_in[0];
    const int*   ei      = (const int*)d_in[1];
    const float* W       = (const float*)d_in[2];
    const float* att_src = (const float*)d_in[3];
    const float* att_dst = (const float*)d_in[4];
    const float* bias    = (const float*)d_in[5];
    float* out = (float*)d_out;

    int N = in_sizes[0] / IN_DIM;
    int E = in_sizes[1] / 2;
    int Etot = E + N;
    int nblocks = (N + SCAN_B - 1) / SCAN_B;

    dim3 ggrid(HC / BN, (N + BM - 1) / BM);
    gemm_kernel<<<ggrid, 256>>>(x, W, att_src, att_dst, N);

    deg_init_kernel<<<(N + 255) / 256, 256>>>(N);
    deg_hist_kernel<<<(E + 255) / 256, 256>>>(ei, E);
    scan1_kernel<<<nblocks, SCAN_B>>>(N);
    scan2_kernel<<<1, SCAN_B>>>(nblocks);
    scan3_kernel<<<(N + 255) / 256, 256>>>(N);
    fill_kernel<<<(Etot + 255) / 256, 256>>>(ei, E, N);

    aggregate_kernel<<<(N * 32 + 255) / 256, 256>>>(bias, out, N);
}

// round 5
// speedup vs baseline: 1.9247x; 1.2043x over previous
#include <cuda_runtime.h>
#include <cuda_bf16.h>
#include <cuda_fp16.h>
#include <math.h>

#define NMAX 50000
#define EMAX 800000
#define ETOTMAX (NMAX + EMAX)
#define IN_DIM 128
#define HC 256
#define HEADS 4
#define CDIM 64
#define NEG_SLOPE 0.2f
#define SCAN_B 512

// ---------------- scratch ----------------
__device__ __half d_hh[(size_t)NMAX * HC];    // projected features, fp16 [N, 256]
__device__ float d_asrc[NMAX * HEADS];
__device__ float d_adst[NMAX * HEADS];
__device__ float d_e[(size_t)ETOTMAX * HEADS]; // per-edge exp(logit), CSR order
__device__ int d_deg[NMAX];
__device__ int d_ptr[NMAX];
__device__ int d_work[NMAX];
__device__ int d_csr_src[ETOTMAX];
__device__ int d_blocksums[SCAN_B];
__device__ int d_blockoff[SCAN_B];

__device__ __forceinline__ float lrelu(float v) {
    return v > 0.0f ? v : NEG_SLOPE * v;
}

// ---------------- Kernel 1: SGEMM h = x @ W (FFMA2, 128x64 tile, dbuf) ---------
#define BM 128
#define BN 64
#define BK 16
#define NKT (IN_DIM / BK)   // 8 k-tiles

__global__ void gemm_kernel(const float* __restrict__ A, const float* __restrict__ B,
                            const float* __restrict__ att_src,
                            const float* __restrict__ att_dst, int M) {
    __shared__ float As[2][BK][BM];   // transposed A tiles
    __shared__ float Bs[2][BK][BN];

    int bx = blockIdx.x;             // head (BN == CDIM)
    int by = blockIdx.y;
    int tid = threadIdx.x;
    int tx = tid & 15;               // col group: cols tx*4 .. tx*4+3
    int ty = tid >> 4;               // row group: rows ty*8 .. ty*8+7
    int row0 = by * BM;
    int col0 = bx * BN;

    // accumulators: acc[i2][j] packs rows (ty*8+2*i2, ty*8+2*i2+1), col tx*4+j
    unsigned long long acc[4][4];
    #pragma unroll
    for (int i = 0; i < 4; i++)
        #pragma unroll
        for (int j = 0; j < 4; j++) acc[i][j] = 0ULL;

    // A-tile loader coords: r = tid>>1 (0..127), c0 = (tid&1)*8
    int ar = tid >> 1;
    int ac0 = (tid & 1) * 8;
    // B-tile loader coords: br = tid>>4 (0..15), bc = (tid&15)*4
    int br = tid >> 4;
    int bc = (tid & 15) * 4;

    float4 pa0, pa1, pb;

    // prologue: fetch tile 0
    {
        int grow = row0 + ar;
        if (grow < M) {
            pa0 = *(const float4*)(A + (size_t)grow * IN_DIM + ac0);
            pa1 = *(const float4*)(A + (size_t)grow * IN_DIM + ac0 + 4);
        } else {
            pa0 = make_float4(0.f, 0.f, 0.f, 0.f);
            pa1 = pa0;
        }
        pb = *(const float4*)(B + (size_t)br * HC + col0 + bc);
    }
    // store tile 0 to buf 0
    As[0][ac0 + 0][ar] = pa0.x; As[0][ac0 + 1][ar] = pa0.y;
    As[0][ac0 + 2][ar] = pa0.z; As[0][ac0 + 3][ar] = pa0.w;
    As[0][ac0 + 4][ar] = pa1.x; As[0][ac0 + 5][ar] = pa1.y;
    As[0][ac0 + 6][ar] = pa1.z; As[0][ac0 + 7][ar] = pa1.w;
    *(float4*)(&Bs[0][br][bc]) = pb;
    __syncthreads();

    #pragma unroll
    for (int kt = 0; kt < NKT; kt++) {
        int cur = kt & 1;
        // prefetch next tile into registers
        if (kt < NKT - 1) {
            int k0 = (kt + 1) * BK;
            int grow = row0 + ar;
            if (grow < M) {
                pa0 = *(const float4*)(A + (size_t)grow * IN_DIM + k0 + ac0);
                pa1 = *(const float4*)(A + (size_t)grow * IN_DIM + k0 + ac0 + 4);
            } else {
                pa0 = make_float4(0.f, 0.f, 0.f, 0.f);
                pa1 = pa0;
            }
            pb = *(const float4*)(B + (size_t)(k0 + br) * HC + col0 + bc);
        }

        // compute on buf cur
        #pragma unroll
        for (int k = 0; k < BK; k++) {
            const ulonglong2* ap = (const ulonglong2*)(&As[cur][k][ty * 8]);
            ulonglong2 a01 = ap[0];
            ulonglong2 a23 = ap[1];
            unsigned long long a64[4] = {a01.x, a01.y, a23.x, a23.y};
            float4 b4 = *(const float4*)(&Bs[cur][k][tx * 4]);
            float bb[4] = {b4.x, b4.y, b4.z, b4.w};
            unsigned long long bp[4];
            #pragma unroll
            for (int j = 0; j < 4; j++)
                asm("mov.b64 %0, {%1, %1};" : "=l"(bp[j]) : "f"(bb[j]));
            #pragma unroll
            for (int i2 = 0; i2 < 4; i2++)
                #pragma unroll
                for (int j = 0; j < 4; j++)
                    asm("fma.rn.f32x2 %0, %1, %2, %0;"
                        : "+l"(acc[i2][j]) : "l"(a64[i2]), "l"(bp[j]));
        }

        if (kt < NKT - 1) {
            int nb = cur ^ 1;
            As[nb][ac0 + 0][ar] = pa0.x; As[nb][ac0 + 1][ar] = pa0.y;
            As[nb][ac0 + 2][ar] = pa0.z; As[nb][ac0 + 3][ar] = pa0.w;
            As[nb][ac0 + 4][ar] = pa1.x; As[nb][ac0 + 5][ar] = pa1.y;
            As[nb][ac0 + 6][ar] = pa1.z; As[nb][ac0 + 7][ar] = pa1.w;
            *(float4*)(&Bs[nb][br][bc]) = pb;
            __syncthreads();
        }
    }

    // unpack: accf[rr][j], rr = 0..7 local row (ty*8 + rr)
    float accf[8][4];
    #pragma unroll
    for (int i2 = 0; i2 < 4; i2++)
        #pragma unroll
        for (int j = 0; j < 4; j++) {
            float lo, hi;
            asm("mov.b64 {%0, %1}, %2;" : "=f"(lo), "=f"(hi) : "l"(acc[i2][j]));
            accf[2 * i2][j] = lo;
            accf[2 * i2 + 1][j] = hi;
        }

    // store h as fp16
    #pragma unroll
    for (int rr = 0; rr < 8; rr++) {
        int grow = row0 + ty * 8 + rr;
        if (grow < M) {
            __half2 p0 = __floats2half2_rn(accf[rr][0], accf[rr][1]);
            __half2 p1 = __floats2half2_rn(accf[rr][2], accf[rr][3]);
            uint2 pk;
            pk.x = *(unsigned*)&p0;
            pk.y = *(unsigned*)&p1;
            *(uint2*)(d_hh + (size_t)grow * HC + col0 + tx * 4) = pk;
        }
    }

    // fused attention-dot epilogue (fp32; block owns full head bx)
    int head = bx;
    float sw[4], dw[4];
    #pragma unroll
    for (int j = 0; j < 4; j++) {
        sw[j] = __ldg(&att_src[head * CDIM + tx * 4 + j]);
        dw[j] = __ldg(&att_dst[head * CDIM + tx * 4 + j]);
    }
    #pragma unroll
    for (int rr = 0; rr < 8; rr++) {
        float s = accf[rr][0] * sw[0] + accf[rr][1] * sw[1]
                + accf[rr][2] * sw[2] + accf[rr][3] * sw[3];
        float dd = accf[rr][0] * dw[0] + accf[rr][1] * dw[1]
                 + accf[rr][2] * dw[2] + accf[rr][3] * dw[3];
        #pragma unroll
        for (int o = 1; o < 16; o <<= 1) {
            s  += __shfl_xor_sync(0xFFFFFFFFu, s, o);
            dd += __shfl_xor_sync(0xFFFFFFFFu, dd, o);
        }
        int grow = row0 + ty * 8 + rr;
        if (tx == 0 && grow < M) {
            d_asrc[grow * HEADS + head] = s;
            d_adst[grow * HEADS + head] = dd;
        }
    }
}

// ---------------- CSR build ------------------------------------------------------
__global__ void deg_init_kernel(int N) {
    int i = blockIdx.x * blockDim.x + threadIdx.x;
    if (i < N) d_deg[i] = 1;   // self loop
}

__global__ void deg_hist_kernel(const int* __restrict__ ei, int E) {
    int i = blockIdx.x * blockDim.x + threadIdx.x;
    if (i < E) atomicAdd(&d_deg[ei[E + i]], 1);
}

__global__ void scan1_kernel(int N) {
    __shared__ int sm[SCAN_B];
    int b = blockIdx.x, t = threadIdx.x;
    int i = b * SCAN_B + t;
    int v = (i < N) ? d_deg[i] : 0;
    sm[t] = v;
    __syncthreads();
    #pragma unroll
    for (int o = 1; o < SCAN_B; o <<= 1) {
        int x = (t >= o) ? sm[t - o] : 0;
        __syncthreads();
        sm[t] += x;
        __syncthreads();
    }
    if (i < N) d_ptr[i] = sm[t] - v;          // exclusive
    if (t == SCAN_B - 1) d_blocksums[b] = sm[t];
}

__global__ void scan2_kernel(int nblocks) {
    __shared__ int sm[SCAN_B];
    int t = threadIdx.x;
    int v = (t < nblocks) ? d_blocksums[t] : 0;
    sm[t] = v;
    __syncthreads();
    #pragma unroll
    for (int o = 1; o < SCAN_B; o <<= 1) {
        int x = (t >= o) ? sm[t - o] : 0;
        __syncthreads();
        sm[t] += x;
        __syncthreads();
    }
    if (t < nblocks) d_blockoff[t] = sm[t] - v;
}

__global__ void scan3_kernel(int N) {
    int i = blockIdx.x * blockDim.x + threadIdx.x;
    if (i < N) {
        int p = d_ptr[i] + d_blockoff[i / SCAN_B];
        d_ptr[i] = p;
        d_work[i] = p;
    }
}

// fill CSR + compute per-edge exp(leakyrelu(logit)) once per edge
__global__ void fill_kernel(const int* __restrict__ ei, int E, int N) {
    int i = blockIdx.x * blockDim.x + threadIdx.x;
    int Etot = E + N;
    if (i >= Etot) return;
    int s, d;
    if (i < E) { s = ei[i]; d = ei[E + i]; } else { s = d = i - E; }
    int pos = atomicAdd(&d_work[d], 1);
    d_csr_src[pos] = s;
    float4 as = *(const float4*)(d_asrc + s * HEADS);
    float4 ad = *(const float4*)(d_adst + d * HEADS);
    float4 ev;
    ev.x = __expf(lrelu(as.x + ad.x));
    ev.y = __expf(lrelu(as.y + ad.y));
    ev.z = __expf(lrelu(as.z + ad.z));
    ev.w = __expf(lrelu(as.w + ad.w));
    *(float4*)(d_e + (size_t)pos * HEADS) = ev;
}

// ---------------- fused softmax + aggregate (warp per node) ----------------------
__device__ __forceinline__ void agg_edge(int i, int lane,
                                         float* num_x, float* num_y, float* dn) {
    int s = __ldg(&d_csr_src[i]);
    float4 e = *(const float4*)(d_e + (size_t)i * HEADS);
    const __half2* hs = (const __half2*)(d_hh + (size_t)s * HC);
    float2 f0 = __half22float2(hs[lane]);
    float2 f1 = __half22float2(hs[32 + lane]);
    float2 f2 = __half22float2(hs[64 + lane]);
    float2 f3 = __half22float2(hs[96 + lane]);
    num_x[0] += e.x * f0.x;  num_y[0] += e.x * f0.y;
    num_x[1] += e.y * f1.x;  num_y[1] += e.y * f1.y;
    num_x[2] += e.z * f2.x;  num_y[2] += e.z * f2.y;
    num_x[3] += e.w * f3.x;  num_y[3] += e.w * f3.y;
    dn[0] += e.x; dn[1] += e.y; dn[2] += e.z; dn[3] += e.w;
}

__global__ void aggregate_kernel(const float* __restrict__ bias,
                                 float* __restrict__ out, int N) {
    int w = (blockIdx.x * blockDim.x + threadIdx.x) >> 5;
    int lane = threadIdx.x & 31;
    if (w >= N) return;
    int r0 = d_ptr[w];
    int r1 = r0 + d_deg[w];

    float num_x[4] = {0.f, 0.f, 0.f, 0.f};
    float num_y[4] = {0.f, 0.f, 0.f, 0.f};
    float dn[4] = {0.f, 0.f, 0.f, 0.f};

    int i = r0;
    for (; i + 2 <= r1; i += 2) {
        agg_edge(i, lane, num_x, num_y, dn);
        agg_edge(i + 1, lane, num_x, num_y, dn);
    }
    if (i < r1) agg_edge(i, lane, num_x, num_y, dn);

    float i0 = 1.f / dn[0], i1 = 1.f / dn[1], i2 = 1.f / dn[2], i3 = 1.f / dn[3];
    float vx = (num_x[0] * i0 + num_x[1] * i1 + num_x[2] * i2 + num_x[3] * i3) * 0.25f
             + __ldg(&bias[lane * 2]);
    float vy = (num_y[0] * i0 + num_y[1] * i1 + num_y[2] * i2 + num_y[3] * i3) * 0.25f
             + __ldg(&bias[lane * 2 + 1]);
    float2 o;
    o.x = vx > 0.f ? vx : expm1f(vx);
    o.y = vy > 0.f ? vy : expm1f(vy);
    *(float2*)(out + (size_t)w * CDIM + lane * 2) = o;
}

// ---------------- launch ---------------------------------------------------------
extern "C" void kernel_launch(void* const* d_in, const int* in_sizes, int n_in,
                              void* d_out, int out_size) {
    const float* x       = (const float*)d_in[0];
    const int*   ei      = (const int*)d_in[1];
    const float* W       = (const float*)d_in[2];
    const float* att_src = (const float*)d_in[3];
    const float* att_dst = (const float*)d_in[4];
    const float* bias    = (const float*)d_in[5];
    float* out = (float*)d_out;

    int N = in_sizes[0] / IN_DIM;
    int E = in_sizes[1] / 2;
    int Etot = E + N;
    int nblocks = (N + SCAN_B - 1) / SCAN_B;

    dim3 ggrid(HC / BN, (N + BM - 1) / BM);
    gemm_kernel<<<ggrid, 256>>>(x, W, att_src, att_dst, N);

    deg_init_kernel<<<(N + 255) / 256, 256>>>(N);
    deg_hist_kernel<<<(E + 255) / 256, 256>>>(ei, E);
    scan1_kernel<<<nblocks, SCAN_B>>>(N);
    scan2_kernel<<<1, SCAN_B>>>(nblocks);
    scan3_kernel<<<(N + 255) / 256, 256>>>(N);
    fill_kernel<<<(Etot + 255) / 256, 256>>>(ei, E, N);

    aggregate_kernel<<<(N * 32 + 255) / 256, 256>>>(bias, out, N);
}